// round 5
// baseline (speedup 1.0000x reference)
#include <cuda_runtime.h>
#include <cuda_bf16.h>
#include <cstdint>
#include <math.h>

#define B_ROWS 32768
#define C_CLS  1000
#define KPAD   1024
#define EPSU   1e-6f
#define NORMF  0.031622776601683794f   // 1/sqrt(1000)

// ---------------- scratch (__device__ globals; no allocations) --------------
__device__ __nv_bfloat16 g_Abf[(size_t)B_ROWS * KPAD];  // p_tar bf16, K padded
__device__ __nv_bfloat16 g_Ebf[(size_t)B_ROWS * KPAD];  // exp(z) bf16, padded 0
__device__ __nv_bfloat16 g_Bbf1[(size_t)KPAD * KPAD];   // bank bf16   [n][k]
__device__ __nv_bfloat16 g_Bbf2[(size_t)KPAD * KPAD];   // bank^T bf16 [n][k]
__device__ float g_rowsum[B_ROWS];
__device__ float g_sums[(size_t)C_CLS * C_CLS];
__device__ float g_count[C_CLS];
__device__ int   g_label[B_ROWS];

// ---------------------------------------------------------------------------
__global__ void zero_kernel() {
    int i = blockIdx.x * blockDim.x + threadIdx.x;
    if (i < C_CLS * C_CLS) g_sums[i] = 0.0f;
    if (i < B_ROWS)        g_rowsum[i] = 0.0f;
    if (i < C_CLS)         g_count[i] = 0.0f;
}

// fused: p_tar -> bf16 padded (g_Abf) + argmax(p_tar) + argmax(p_vlm) + agree
// one block (256 thr) per row; pair-wise (bf16x2) stores
__global__ void __launch_bounds__(256) prep_kernel(const float* __restrict__ p_tar,
                                                   const float* __restrict__ p_vlm) {
    const int row = blockIdx.x;
    const int t   = threadIdx.x;
    const float2* pt2 = reinterpret_cast<const float2*>(p_tar + (size_t)row * C_CLS);
    const float2* pv2 = reinterpret_cast<const float2*>(p_vlm + (size_t)row * C_CLS);
    uint32_t* arow = reinterpret_cast<uint32_t*>(g_Abf + (size_t)row * KPAD);

    float vt = -1.0f, vv = -1.0f;
    int   it = 0,     iv = 0;
    #pragma unroll
    for (int kp = t; kp < KPAD / 2; kp += 256) {
        int k = 2 * kp;
        if (k < C_CLS) {
            float2 a = pt2[kp];
            float2 b = pv2[kp];
            if (a.x > vt) { vt = a.x; it = k; }
            if (a.y > vt) { vt = a.y; it = k + 1; }
            if (b.x > vv) { vv = b.x; iv = k; }
            if (b.y > vv) { vv = b.y; iv = k + 1; }
            __nv_bfloat162 h2 = __float22bfloat162_rn(make_float2(a.x, a.y));
            arow[kp] = *reinterpret_cast<uint32_t*>(&h2);
        } else {
            arow[kp] = 0u;
        }
    }
    // warp reduce (ties -> smaller index)
    const int lane = t & 31;
    #pragma unroll
    for (int off = 16; off > 0; off >>= 1) {
        float ov = __shfl_down_sync(0xFFFFFFFFu, vt, off);
        int   oi = __shfl_down_sync(0xFFFFFFFFu, it, off);
        if (ov > vt || (ov == vt && oi < it)) { vt = ov; it = oi; }
        ov = __shfl_down_sync(0xFFFFFFFFu, vv, off);
        oi = __shfl_down_sync(0xFFFFFFFFu, iv, off);
        if (ov > vv || (ov == vv && oi < iv)) { vv = ov; iv = oi; }
    }
    __shared__ float swt[8], swv[8];
    __shared__ int   sit[8], siv[8];
    if (lane == 0) { swt[t >> 5] = vt; sit[t >> 5] = it; swv[t >> 5] = vv; siv[t >> 5] = iv; }
    __syncthreads();
    if (t == 0) {
        float bt = swt[0], bv = swv[0];
        int   bi = sit[0], bj = siv[0];
        #pragma unroll
        for (int w = 1; w < 8; w++) {
            if (swt[w] > bt || (swt[w] == bt && sit[w] < bi)) { bt = swt[w]; bi = sit[w]; }
            if (swv[w] > bv || (swv[w] == bv && siv[w] < bj)) { bv = swv[w]; bj = siv[w]; }
        }
        if (bi == bj) { g_label[row] = bi; atomicAdd(&g_count[bi], 1.0f); }
        else          { g_label[row] = -1; }
    }
}

__global__ void convB_kernel(const float* __restrict__ bank) {
    int i = blockIdx.x * blockDim.x + threadIdx.x;
    if (i >= KPAD * KPAD) return;
    int n = i >> 10, k = i & (KPAD - 1);
    bool v = (n < C_CLS) && (k < C_CLS);
    g_Bbf1[i] = v ? __float2bfloat16(bank[(size_t)n * C_CLS + k]) : __float2bfloat16(0.0f);
    g_Bbf2[i] = v ? __float2bfloat16(bank[(size_t)k * C_CLS + n]) : __float2bfloat16(0.0f);
}

__global__ void scatter_kernel(const float* __restrict__ p_tar) {
    int row = blockIdx.x;
    int c   = g_label[row];
    if (c < 0) return;
    const float* pt  = p_tar + (size_t)row * C_CLS;
    float*       dst = g_sums + (size_t)c * C_CLS;
    for (int k = threadIdx.x; k < C_CLS; k += blockDim.x)
        atomicAdd(&dst[k], pt[k]);
}

__global__ void bank_kernel(const float* __restrict__ bank,
                            const float* __restrict__ alpha,
                            float* __restrict__ out_bank) {
    int i = blockIdx.x * blockDim.x + threadIdx.x;
    if (i >= C_CLS * C_CLS) return;
    int   c   = i / C_CLS;
    float a   = alpha[0];
    float cnt = g_count[c];
    float b   = bank[i];
    out_bank[i] = (cnt > 0.0f) ? (a * b + (1.0f - a) * (g_sums[i] / cnt)) : b;
}

// ---------------------------------------------------------------------------
// HMMA GEMM (NT, bf16/fp32): D[bm:+256, bn:+128] = A * B^T
// 256 thr, 8 warps (4m x 2n), warp tile 64x64, BK=32, cp.async 3-stage
#define BM     256
#define BN     128
#define BK     32
#define STAGES 3
#define LDSP   40                   // padded smem row stride (bf16 elems)
#define NC     (KPAD / BK)          // 32
#define ST_A_BYTES (BM * LDSP * 2)  // 20480
#define ST_B_BYTES (BN * LDSP * 2)  // 10240
#define ST_BYTES   (ST_A_BYTES + ST_B_BYTES)
#define SMEM_TOTAL (STAGES * ST_BYTES)  // 92160

__device__ __forceinline__ uint32_t smem_u32(const void* p) {
    uint32_t a;
    asm("{ .reg .u64 t; cvta.to.shared.u64 t, %1; cvt.u32.u64 %0, t; }"
        : "=r"(a) : "l"(p));
    return a;
}
__device__ __forceinline__ void ldmx4(uint32_t* r, uint32_t addr) {
    asm volatile("ldmatrix.sync.aligned.m8n8.x4.shared.b16 {%0,%1,%2,%3}, [%4];"
                 : "=r"(r[0]), "=r"(r[1]), "=r"(r[2]), "=r"(r[3]) : "r"(addr));
}
__device__ __forceinline__ void mma16816(float* c, const uint32_t* a,
                                         uint32_t b0, uint32_t b1) {
    asm volatile("mma.sync.aligned.m16n8k16.row.col.f32.bf16.bf16.f32 "
                 "{%0,%1,%2,%3}, {%4,%5,%6,%7}, {%8,%9}, {%0,%1,%2,%3};"
                 : "+f"(c[0]), "+f"(c[1]), "+f"(c[2]), "+f"(c[3])
                 : "r"(a[0]), "r"(a[1]), "r"(a[2]), "r"(a[3]), "r"(b0), "r"(b1));
}
#define CP16(dst, src) \
    asm volatile("cp.async.cg.shared.global [%0], [%1], 16;" :: "r"(dst), "l"(src))
#define CP_COMMIT() asm volatile("cp.async.commit_group;")
#define CP_WAIT1()  asm volatile("cp.async.wait_group 1;")

__global__ void __launch_bounds__(256, 1)
gemm_mma(const float* __restrict__ p_vlm,
         float* __restrict__ out,
         int mode) {
    extern __shared__ char smem[];
    const uint32_t sb = smem_u32(smem);

    const __nv_bfloat16* __restrict__ A  = (mode == 1) ? g_Abf  : g_Ebf;
    const __nv_bfloat16* __restrict__ Bm = (mode == 1) ? g_Bbf1 : g_Bbf2;

    const int t   = threadIdx.x;
    const int wid = t >> 5;
    const int l   = t & 31;
    const int wm  = wid >> 1;            // 0..3 -> m offset wm*64
    const int wn  = wid & 1;             // 0..1 -> n offset wn*64
    const int bm  = blockIdx.y * BM;
    const int bn  = blockIdx.x * BN;

    const uint4* gA = reinterpret_cast<const uint4*>(A);
    const uint4* gB = reinterpret_cast<const uint4*>(Bm);
    const int r = t >> 2, u = t & 3;     // loader mapping (row, 16B-col)

    float acc[4][8][4];
    #pragma unroll
    for (int mi = 0; mi < 4; mi++)
        #pragma unroll
        for (int ni = 0; ni < 8; ni++)
            #pragma unroll
            for (int k = 0; k < 4; k++) acc[mi][ni][k] = 0.0f;

    const int aRow = wm * 64 + (l & 15);
    const int aK   = (l & 16) ? 8 : 0;
    const int bRow = wn * 64 + (l & 7) + ((l & 16) ? 8 : 0);
    const int bK   = (l & 8) ? 8 : 0;

    // ---- issue stage s loads (chunk s) ----
    auto load_stage = [&](int chunk, int buf) {
        const int kc = chunk * (BK / 8);
        const uint32_t dA = sb + buf * ST_BYTES;
        const uint32_t dB = dA + ST_A_BYTES;
        #pragma unroll
        for (int i = 0; i < 4; i++) {           // A: 256 rows
            int rr = r + 64 * i;
            CP16(dA + rr * (LDSP * 2) + u * 16,
                 (const void*)(gA + (size_t)(bm + rr) * 128 + kc + u));
        }
        #pragma unroll
        for (int i = 0; i < 2; i++) {           // B: 128 rows
            int rr = r + 64 * i;
            CP16(dB + rr * (LDSP * 2) + u * 16,
                 (const void*)(gB + (size_t)(bn + rr) * 128 + kc + u));
        }
    };

    #pragma unroll
    for (int s = 0; s < STAGES - 1; ++s) { load_stage(s, s); CP_COMMIT(); }

    for (int c = 0; c < NC; ++c) {
        CP_WAIT1();
        __syncthreads();
        const int buf = c % STAGES;
        const uint32_t baseA = sb + buf * ST_BYTES;
        const uint32_t baseB = baseA + ST_A_BYTES;

        #pragma unroll
        for (int s = 0; s < 2; ++s) {           // two k16 steps
            uint32_t af[4][4];
            #pragma unroll
            for (int mi = 0; mi < 4; mi++)
                ldmx4(af[mi], baseA + 2 * ((aRow + mi * 16) * LDSP + s * 16 + aK));
            uint32_t bf[4][4];
            #pragma unroll
            for (int g = 0; g < 4; g++)
                ldmx4(bf[g], baseB + 2 * ((bRow + g * 16) * LDSP + s * 16 + bK));
            #pragma unroll
            for (int mi = 0; mi < 4; mi++)
                #pragma unroll
                for (int g = 0; g < 4; g++) {
                    mma16816(acc[mi][2 * g],     af[mi], bf[g][0], bf[g][1]);
                    mma16816(acc[mi][2 * g + 1], af[mi], bf[g][2], bf[g][3]);
                }
        }

        const int nc_ = c + STAGES - 1;
        if (nc_ < NC) load_stage(nc_, nc_ % STAGES);
        CP_COMMIT();
        __syncthreads();
    }

    // ---- epilogue ----
    // rows: bm + wm*64 + mi*16 + (l>>2) + h*8 ; cols: bn + wn*64 + ni*8 + (l&3)*2
    if (mode == 1) {
        #pragma unroll
        for (int mi = 0; mi < 4; mi++) {
            #pragma unroll
            for (int h = 0; h < 2; h++) {
                const int row = bm + wm * 64 + mi * 16 + (l >> 2) + h * 8;
                float rs = 0.0f;
                #pragma unroll
                for (int ni = 0; ni < 8; ni++) {
                    const int col = bn + wn * 64 + ni * 8 + (l & 3) * 2;
                    float v0 = acc[mi][ni][h * 2 + 0];
                    float v1 = acc[mi][ni][h * 2 + 1];
                    float e0 = (col     < C_CLS) ? __expf(v0 * NORMF) : 0.0f;
                    float e1 = (col + 1 < C_CLS) ? __expf(v1 * NORMF) : 0.0f;
                    __nv_bfloat162 h2 = __float22bfloat162_rn(make_float2(e0, e1));
                    *(uint32_t*)&g_Ebf[(size_t)row * KPAD + col] =
                        *reinterpret_cast<uint32_t*>(&h2);
                    rs += __bfloat162float(h2.x) + __bfloat162float(h2.y);
                }
                rs += __shfl_xor_sync(0xFFFFFFFFu, rs, 1);
                rs += __shfl_xor_sync(0xFFFFFFFFu, rs, 2);
                if ((l & 3) == 0) atomicAdd(&g_rowsum[row], rs);
            }
        }
    } else {
        #pragma unroll
        for (int mi = 0; mi < 4; mi++) {
            #pragma unroll
            for (int h = 0; h < 2; h++) {
                const int row = bm + wm * 64 + mi * 16 + (l >> 2) + h * 8;
                const float inv = 1.0f / g_rowsum[row];
                const float* pvrow = p_vlm + (size_t)row * C_CLS;
                float*       orow  = out   + (size_t)row * C_CLS;
                #pragma unroll
                for (int ni = 0; ni < 8; ni++) {
                    const int col = bn + wn * 64 + ni * 8 + (l & 3) * 2;
                    #pragma unroll
                    for (int e = 0; e < 2; e++) {
                        int n = col + e;
                        if (n < C_CLS) {
                            float pt  = acc[mi][ni][h * 2 + e] * inv;
                            float pv  = __ldg(pvrow + n);
                            float eut = __expf(pt * __logf(pt + EPSU));
                            float euv = __expf(pv * __logf(pv + EPSU));
                            orow[n] = (eut * pt + euv * pv) / (eut + euv);
                        }
                    }
                }
            }
        }
    }
}

// ---------------------------------------------------------------------------
extern "C" void kernel_launch(void* const* d_in, const int* in_sizes, int n_in,
                              void* d_out, int out_size) {
    const float* p_tar = (const float*)d_in[0];
    const float* p_vlm = (const float*)d_in[1];
    const float* alpha = (const float*)d_in[2];
    const float* bank  = (const float*)d_in[3];
    float* out      = (float*)d_out;                       // p_mix [B,C]
    float* out_bank = out + (size_t)B_ROWS * C_CLS;        // bank_new [C,C]

    static int attr_set = 0;
    if (!attr_set) {
        cudaFuncSetAttribute(gemm_mma, cudaFuncAttributeMaxDynamicSharedMemorySize,
                             SMEM_TOTAL);
        attr_set = 1;
    }

    zero_kernel<<<(C_CLS * C_CLS + 255) / 256, 256>>>();
    prep_kernel<<<B_ROWS, 256>>>(p_tar, p_vlm);
    convB_kernel<<<(KPAD * KPAD + 255) / 256, 256>>>(bank);
    scatter_kernel<<<B_ROWS, 128>>>(p_tar);
    bank_kernel<<<(C_CLS * C_CLS + 255) / 256, 256>>>(bank, alpha, out_bank);

    dim3 gg(KPAD / BN, B_ROWS / BM);  // (8, 128)
    gemm_mma<<<gg, 256, SMEM_TOTAL>>>(nullptr, nullptr, 1);
    gemm_mma<<<gg, 256, SMEM_TOTAL>>>(p_vlm, out, 2);
}